// round 1
// baseline (speedup 1.0000x reference)
#include <cuda_runtime.h>
#include <math.h>

// Problem constants
#define NB   8
#define CC   256
#define HH   64
#define WW   64
#define LL   4096          // HH*WW
#define GG   8
#define KK   9
#define CG   32            // CC/GG
#define MTOT 32768         // NB*LL
#define OMC  216           // GG*KK*3

// Scratch (static device globals — allowed; no runtime allocation)
__device__ float g_value[(size_t)MTOT * CC];   // (n, l, c)   value projection
__device__ float g_omin [(size_t)MTOT * CC];   // (n, c, l)   depthwise conv out
__device__ float g_om   [(size_t)MTOT * OMC];  // (n, l, 216) offsets+masks
__device__ float g_out2 [(size_t)MTOT * CC];   // (n, l, c)   sampled*mask

// ---------------------------------------------------------------------------
// Depthwise 3x3 conv, SAME zero pad.  out (n,c,l) = b[c] + sum w[c,ky,kx]*x[...]
// ---------------------------------------------------------------------------
__global__ void dwconv_kernel(const float* __restrict__ x,
                              const float* __restrict__ w,
                              const float* __restrict__ b)
{
    int idx = blockIdx.x * 256 + threadIdx.x;   // n*C*L + c*L + l
    int l = idx & (LL - 1);
    int c = (idx >> 12) & (CC - 1);
    int yy = l >> 6;
    int xx = l & (WW - 1);
    const float* wp = w + c * 9;
    const float* xp = x + ((size_t)(idx >> 12)) * LL;  // x[n][c] base
    float acc = b[c];
#pragma unroll
    for (int ky = 0; ky < 3; ky++) {
        int y = yy + ky - 1;
        if ((unsigned)y < HH) {
#pragma unroll
            for (int kx = 0; kx < 3; kx++) {
                int xc = xx + kx - 1;
                if ((unsigned)xc < WW)
                    acc = fmaf(wp[ky * 3 + kx], xp[y * WW + xc], acc);
            }
        }
    }
    g_omin[idx] = acc;
}

// ---------------------------------------------------------------------------
// TN GEMM:  C[m, j] = sum_k A(k, m) * B[j, k] + bias[j]
//   A stored (n, k, l):   element (k, m=(n,l)) at A + n*C*L + k*L + l
//   B (Ncols, 256) row-major
//   which == 0 : A = x     -> g_value (row stride 256)
//   which == 1 : A = g_omin-> g_om    (row stride 216)
// 128x128x8 tile, 256 threads, 8x8 per-thread microtile (n-fast store mapping)
// ---------------------------------------------------------------------------
__global__ __launch_bounds__(256, 2)
void gemm_tn(const float* __restrict__ Aext,
             const float* __restrict__ B,
             const float* __restrict__ bias,
             int Ncols, int which)
{
    __shared__ float As[8][128];
    __shared__ float Bs[8][128];

    const float* A  = (which == 0) ? Aext : g_omin;
    float*       Cm = (which == 0) ? g_value : g_om;

    int m0   = blockIdx.x * 128;
    int nimg = m0 >> 12;           // m0 / LL
    int l0   = m0 & (LL - 1);
    const float* Ab = A + (size_t)nimg * (CC * LL) + l0;
    int jt = blockIdx.y * 128;

    int tid = threadIdx.x;
    int tx = tid & 15;             // column direction (n-fast)
    int ty = tid >> 4;             // row direction

    int ka = tid >> 5;             // A-load: row of BK
    int ma = (tid << 2) & 127;     // A-load: col (float4)
    int jb = tid >> 1;             // B-load: row j
    int kb = (tid & 1) << 2;       // B-load: k offset (float4)
    bool bvalid = (jt + jb) < Ncols;
    const float* Bp = B + (size_t)(jt + jb) * CC + kb;

    float acc[8][8];
#pragma unroll
    for (int i = 0; i < 8; i++)
#pragma unroll
        for (int j = 0; j < 8; j++) acc[i][j] = 0.f;

    for (int k0 = 0; k0 < CC; k0 += 8) {
        float4 av = *(const float4*)(Ab + (size_t)(k0 + ka) * LL + ma);
        float4 bv = bvalid ? *(const float4*)(Bp + k0)
                           : make_float4(0.f, 0.f, 0.f, 0.f);
        *(float4*)&As[ka][ma] = av;
        Bs[kb + 0][jb] = bv.x;
        Bs[kb + 1][jb] = bv.y;
        Bs[kb + 2][jb] = bv.z;
        Bs[kb + 3][jb] = bv.w;
        __syncthreads();
#pragma unroll
        for (int k = 0; k < 8; k++) {
            float ra[8], rb[8];
#pragma unroll
            for (int i = 0; i < 8; i++) ra[i] = As[k][ty + i * 16];
#pragma unroll
            for (int j = 0; j < 8; j++) rb[j] = Bs[k][tx + j * 16];
#pragma unroll
            for (int i = 0; i < 8; i++)
#pragma unroll
                for (int j = 0; j < 8; j++)
                    acc[i][j] = fmaf(ra[i], rb[j], acc[i][j]);
        }
        __syncthreads();
    }

    float bb[8];
#pragma unroll
    for (int j = 0; j < 8; j++) {
        int jc = jt + tx + j * 16;
        bb[j] = (jc < Ncols) ? bias[jc] : 0.f;
    }
#pragma unroll
    for (int i = 0; i < 8; i++) {
        int m = m0 + ty + i * 16;
        float* Crow = Cm + (size_t)m * Ncols;
#pragma unroll
        for (int j = 0; j < 8; j++) {
            int jc = jt + tx + j * 16;
            if (jc < Ncols) Crow[jc] = acc[i][j] + bb[j];
        }
    }
}

// ---------------------------------------------------------------------------
// Deformable bilinear sampling + mask reduce.
// One warp per (n, l, g); lane = channel within group.
// reads g_om (n,l,216), g_value (n,l,g,cg); writes g_out2 (n,l,c)
// ---------------------------------------------------------------------------
__global__ void sample_kernel()
{
    int warp = (blockIdx.x * blockDim.x + threadIdx.x) >> 5;
    int lane = threadIdx.x & 31;
    int g  = warp & (GG - 1);
    int nl = warp >> 3;              // n*L + l
    int l  = nl & (LL - 1);
    int yy = l >> 6;
    int xx = l & (WW - 1);

    const float* omp = g_om + (size_t)nl * OMC + g * 27;
    const float* vb  = g_value + (size_t)(nl >> 12) * ((size_t)LL * CC)
                     + g * CG + lane;

    float acc = 0.f;
#pragma unroll
    for (int k = 0; k < KK; k++) {
        float offy = omp[2 * k];
        float offx = omp[2 * k + 1];
        float mk   = omp[18 + k];
        float py = (float)(yy + (k / 3) - 1) + offy;
        float px = (float)(xx + (k % 3) - 1) + offx;
        float y0f = floorf(py);
        float x0f = floorf(px);
        float tyf = py - y0f;
        float txf = px - x0f;
        int y0 = (int)y0f;
        int x0 = (int)x0f;

        float s = 0.f;
#pragma unroll
        for (int dy = 0; dy < 2; dy++) {
#pragma unroll
            for (int dx = 0; dx < 2; dx++) {
                int yi = y0 + dy;
                int xi = x0 + dx;
                float wgt = (dy ? tyf : (1.f - tyf)) * (dx ? txf : (1.f - txf));
                if (yi >= 0 && yi < HH && xi >= 0 && xi < WW)
                    s = fmaf(wgt, vb[(size_t)(yi * WW + xi) * CC], s);
            }
        }
        acc = fmaf(mk, s, acc);
    }
    g_out2[(size_t)nl * CC + g * CG + lane] = acc;
}

// ---------------------------------------------------------------------------
// NT GEMM (output projection):  out[n, j, l] = sum_k g_out2[m, k] * op_w[j, k]
// A = g_out2 (M,256) row-major; store transposed to NCHW d_out.
// m-fast thread mapping for coalesced NCHW stores.
// ---------------------------------------------------------------------------
__global__ __launch_bounds__(256, 2)
void gemm_nt_out(const float* __restrict__ B, float* __restrict__ Out)
{
    __shared__ float As[8][128];
    __shared__ float Bs[8][128];

    int m0 = blockIdx.x * 128;
    int jt = blockIdx.y * 128;
    int tid = threadIdx.x;
    int tx = tid & 15;             // m direction (fast for stores)
    int ty = tid >> 4;             // column direction

    int rrow = tid >> 1;           // load: row index (m or j)
    int kk4  = (tid & 1) << 2;     // load: k offset
    const float* Ap = g_out2 + (size_t)(m0 + rrow) * CC + kk4;
    const float* Bp = B       + (size_t)(jt + rrow) * CC + kk4;

    float acc[8][8];
#pragma unroll
    for (int i = 0; i < 8; i++)
#pragma unroll
        for (int j = 0; j < 8; j++) acc[i][j] = 0.f;

    for (int k0 = 0; k0 < CC; k0 += 8) {
        float4 av = *(const float4*)(Ap + k0);
        float4 bv = *(const float4*)(Bp + k0);
        As[kk4 + 0][rrow] = av.x;
        As[kk4 + 1][rrow] = av.y;
        As[kk4 + 2][rrow] = av.z;
        As[kk4 + 3][rrow] = av.w;
        Bs[kk4 + 0][rrow] = bv.x;
        Bs[kk4 + 1][rrow] = bv.y;
        Bs[kk4 + 2][rrow] = bv.z;
        Bs[kk4 + 3][rrow] = bv.w;
        __syncthreads();
#pragma unroll
        for (int k = 0; k < 8; k++) {
            float ra[8], rb[8];
#pragma unroll
            for (int i = 0; i < 8; i++) ra[i] = As[k][tx + i * 16];
#pragma unroll
            for (int j = 0; j < 8; j++) rb[j] = Bs[k][ty + j * 16];
#pragma unroll
            for (int i = 0; i < 8; i++)
#pragma unroll
                for (int j = 0; j < 8; j++)
                    acc[i][j] = fmaf(ra[i], rb[j], acc[i][j]);
        }
        __syncthreads();
    }

    int nimg = m0 >> 12;
    int l0   = m0 & (LL - 1);
    float* Ob = Out + (size_t)nimg * (CC * LL);
#pragma unroll
    for (int i = 0; i < 8; i++) {
        int lloc = l0 + tx + i * 16;
#pragma unroll
        for (int j = 0; j < 8; j++) {
            int jc = jt + ty + j * 16;
            Ob[(size_t)jc * LL + lloc] = acc[i][j];
        }
    }
}

// ---------------------------------------------------------------------------
extern "C" void kernel_launch(void* const* d_in, const int* in_sizes, int n_in,
                              void* d_out, int out_size)
{
    const float* x    = (const float*)d_in[0];
    const float* dw_w = (const float*)d_in[1];
    const float* dw_b = (const float*)d_in[2];
    const float* om_w = (const float*)d_in[3];
    const float* om_b = (const float*)d_in[4];
    const float* vp_w = (const float*)d_in[5];
    const float* vp_b = (const float*)d_in[6];
    const float* op_w = (const float*)d_in[7];
    float* out = (float*)d_out;

    // 1. depthwise conv  -> g_omin
    dwconv_kernel<<<(NB * CC * LL) / 256, 256>>>(x, dw_w, dw_b);

    // 2a. offset/mask GEMM  g_omin @ om_w^T + om_b -> g_om  (216 cols)
    gemm_tn<<<dim3(MTOT / 128, 2), 256>>>(nullptr, om_w, om_b, OMC, 1);

    // 2b. value projection  x @ vp_w^T + vp_b -> g_value  (256 cols)
    gemm_tn<<<dim3(MTOT / 128, 2), 256>>>(x, vp_w, vp_b, CC, 0);

    // 3. deformable sampling -> g_out2
    sample_kernel<<<(MTOT * GG) / 8, 256>>>();

    // 4. output projection g_out2 @ op_w^T -> d_out (NCHW)
    gemm_nt_out<<<dim3(MTOT / 128, 2), 256>>>(op_w, out);
}